// round 4
// baseline (speedup 1.0000x reference)
#include <cuda_runtime.h>
#include <cstdint>

// ---------------------------------------------------------------------------
// BERTHeading via warp-level mma.sync tf32 GEMMs.
//   conv-k row (s,t) = relu( dot(words[s, t:t+k] (contig 768k f32), Wk) + bk )
//   -> GEMM, K_eff = 768k, N = 512.
// Tile: BM=128 x BN=256, K-chunk 32 f32. 8 warps, 64x64 warp tile.
// 4-stage cp.async pipeline, one barrier per chunk, ldmatrix.x4 fragments.
// ---------------------------------------------------------------------------

#define BS      4096
#define EMB     768
#define FEAT    512

#define BM      128
#define BN      256
#define BKF     32
#define KPAD    36
#define ASZ     (BM * KPAD)          // 4608 floats
#define BSZ     (BN * KPAD)          // 9216 floats
#define STG     (ASZ + BSZ)          // 13824 floats / stage
#define STAGES  4
#define SMEM_TOTAL (STAGES * STG * 4)   // 221184 bytes

__device__ float g_A[BS * 20 * FEAT];
__device__ float g_B[BS * 19 * FEAT];
__device__ float g_C[BS * 18 * FEAT];
// transposed + tf32-rounded weights, [512, K] row-major: W1 | W2 | W3 | Wp
__device__ float g_Wt[512 * (768 + 1536 + 2304 + 768)];

#define CP_ASYNC16(saddr, gptr) \
    asm volatile("cp.async.cg.shared.global [%0], [%1], 16;" :: "r"(saddr), "l"(gptr))
#define CP_COMMIT() asm volatile("cp.async.commit_group;" ::: "memory")
#define CP_WAIT3()  asm volatile("cp.async.wait_group 3;" ::: "memory")

__device__ __forceinline__ uint32_t smem_u32(const void* p) {
    uint32_t a;
    asm("{ .reg .u64 t; cvta.to.shared.u64 t, %1; cvt.u32.u64 %0, t; }"
        : "=r"(a) : "l"(p));
    return a;
}

__device__ __forceinline__ void mma_tf32(float* d, const uint32_t* a,
                                         const uint32_t* b) {
    asm volatile(
        "mma.sync.aligned.m16n8k8.row.col.f32.tf32.tf32.f32 "
        "{%0,%1,%2,%3}, {%4,%5,%6,%7}, {%8,%9}, {%0,%1,%2,%3};"
        : "+f"(d[0]), "+f"(d[1]), "+f"(d[2]), "+f"(d[3])
        : "r"(a[0]), "r"(a[1]), "r"(a[2]), "r"(a[3]), "r"(b[0]), "r"(b[1]));
}

// ldmatrix.x4 b16: each 8x8 b16 matrix == 8x4 f32 block; lane l receives
// (row=l/4, f32col=l%4) from each matrix — exactly the tf32 fragment layout.
__device__ __forceinline__ void ldsm_x4(uint32_t* r, uint32_t addr) {
    asm volatile(
        "ldmatrix.sync.aligned.m8n8.x4.shared.b16 {%0,%1,%2,%3}, [%4];"
        : "=r"(r[0]), "=r"(r[1]), "=r"(r[2]), "=r"(r[3]) : "r"(addr));
}

// ---------------------------------------------------------------------------
// Weight transpose + tf32 rounding: W [K,512] -> Wt [512,K] (rna-rounded)
// ---------------------------------------------------------------------------
__global__ void transpose_w(const float* __restrict__ W, float* __restrict__ Wt,
                            int K)
{
    __shared__ float t[32][33];
    const int kb = blockIdx.x * 32, nb = blockIdx.y * 32;
    const int x = threadIdx.x, y = threadIdx.y;   // 32 x 8
    #pragma unroll
    for (int i = 0; i < 32; i += 8)
        t[y + i][x] = W[(size_t)(kb + y + i) * FEAT + nb + x];
    __syncthreads();
    #pragma unroll
    for (int i = 0; i < 32; i += 8) {
        float v = t[x][y + i];
        uint32_t u;
        asm("cvt.rna.tf32.f32 %0, %1;" : "=r"(u) : "f"(v));
        Wt[(size_t)(nb + y + i) * K + kb + x] = __uint_as_float(u);
    }
}

// ---------------------------------------------------------------------------
// tf32 mma.sync GEMM.
//   Y[m, nb..nb+255] = act( A(m,:) @ Wt[nb..nb+255,:]^T + bias )
//   A(m,:) = X + (m/T)*srcStride + (m%T)*768, contiguous K floats.
// Grid: (M/128, 512/256). 256 threads.
// ---------------------------------------------------------------------------
__global__ void __launch_bounds__(256, 1)
gemm_mma(const float* __restrict__ X, const float* __restrict__ Wt,
         const float* __restrict__ bias, float* __restrict__ Yext,
         int sel, int K, int T, int srcStride, int doRelu)
{
    extern __shared__ float smem[];
    float* Y = (sel == 0) ? g_A : (sel == 1) ? g_B : (sel == 2) ? g_C : Yext;

    const int tid  = threadIdx.x;
    const int lane = tid & 31;
    const int wid  = tid >> 5;
    const int wm   = wid & 1;        // 2 m-warps
    const int wn   = wid >> 1;       // 4 n-warps
    const int r    = lane >> 2;      // 0..7
    const int cq   = lane & 3;       // 0..3
    const int lrow = lane & 7;       // ldmatrix row within matrix
    const int mat  = lane >> 3;      // ldmatrix matrix index 0..3

    const int nb = blockIdx.y * BN;
    const uint32_t sbase = smem_u32(smem);

    // ---- loader addresses ----
    // A: row = tid/2 (128 rows), 4 x 16B at koff = (tid&1)*16 floats
    const int am   = blockIdx.x * BM + (tid >> 1);
    const int akof = (tid & 1) * 16;
    const float* aRow = X + (size_t)(am / T) * srcStride
                          + (size_t)(am % T) * EMB + akof;
    const uint32_t aDst = sbase + ((tid >> 1) * KPAD + akof) * 4;
    // B: row = tid (256 rows), 8 x 16B
    const float* bRow = Wt + (size_t)(nb + tid) * K;
    const uint32_t bDst = sbase + (ASZ + tid * KPAD) * 4;

    const int Kc = K / BKF;

    auto load_chunk = [&](int chunk) {
        const uint32_t so = (uint32_t)((chunk & (STAGES - 1)) * STG * 4);
        const int kc = chunk * BKF;
        #pragma unroll
        for (int j = 0; j < 4; j++)
            CP_ASYNC16(aDst + so + j * 16, aRow + kc + j * 4);
        #pragma unroll
        for (int j = 0; j < 8; j++)
            CP_ASYNC16(bDst + so + j * 16, bRow + kc + j * 4);
    };

    float acc[4][8][4];
    #pragma unroll
    for (int mi = 0; mi < 4; mi++)
        #pragma unroll
        for (int nj = 0; nj < 8; nj++)
            #pragma unroll
            for (int q = 0; q < 4; q++) acc[mi][nj][q] = 0.0f;

    // prologue: stages 0..2
    load_chunk(0); CP_COMMIT();
    load_chunk(1); CP_COMMIT();
    load_chunk(2); CP_COMMIT();

    // ldmatrix lane-base offsets (in floats, before *4 bytes):
    //   A matrix (mi, ks): row = wm*64 + mi*16 + (mat&1)*8 + lrow,
    //                      col = ks*8 + (mat>>1)*4
    //   B matrix (njp,ks): row = wn*64 + njp*16 + (mat&1)*8 + lrow, same col
    const uint32_t aFragBase =
        sbase + ((wm * 64 + (mat & 1) * 8 + lrow) * KPAD + (mat >> 1) * 4) * 4;
    const uint32_t bFragBase =
        sbase + (ASZ + (wn * 64 + (mat & 1) * 8 + lrow) * KPAD + (mat >> 1) * 4) * 4;

    for (int c = 0; c < Kc; c++) {
        __syncthreads();                 // readers of chunk c-1 done
        if (c + 3 < Kc) load_chunk(c + 3);
        CP_COMMIT();
        CP_WAIT3();                      // chunk c resident

        const uint32_t so = (uint32_t)((c & (STAGES - 1)) * STG * 4);

        #pragma unroll
        for (int ks = 0; ks < 4; ks++) {
            uint32_t af[4][4];
            #pragma unroll
            for (int mi = 0; mi < 4; mi++)
                ldsm_x4(af[mi], aFragBase + so + (mi * 16 * KPAD + ks * 8) * 4);
            uint32_t bf[4][4];           // [njp][4]: {nj0.b0, nj1.b0, nj0.b1, nj1.b1}
            #pragma unroll
            for (int njp = 0; njp < 4; njp++)
                ldsm_x4(bf[njp], bFragBase + so + (njp * 16 * KPAD + ks * 8) * 4);

            #pragma unroll
            for (int mi = 0; mi < 4; mi++)
                #pragma unroll
                for (int njp = 0; njp < 4; njp++) {
                    uint32_t b0[2] = { bf[njp][0], bf[njp][2] };
                    uint32_t b1[2] = { bf[njp][1], bf[njp][3] };
                    mma_tf32(acc[mi][2 * njp + 0], af[mi], b0);
                    mma_tf32(acc[mi][2 * njp + 1], af[mi], b1);
                }
        }
    }

    // ---- epilogue: bias (+relu), write Y ----
    const int mBase = blockIdx.x * BM + wm * 64 + r;
    const int nBase = nb + wn * 64 + cq * 2;
    float bb[8][2];
    #pragma unroll
    for (int nj = 0; nj < 8; nj++) {
        bb[nj][0] = __ldg(bias + nBase + nj * 8);
        bb[nj][1] = __ldg(bias + nBase + nj * 8 + 1);
    }
    #pragma unroll
    for (int mi = 0; mi < 4; mi++) {
        #pragma unroll
        for (int rr = 0; rr < 2; rr++) {
            float* yr = Y + (size_t)(mBase + mi * 16 + rr * 8) * FEAT;
            #pragma unroll
            for (int nj = 0; nj < 8; nj++) {
                float v0 = acc[mi][nj][rr * 2 + 0] + bb[nj][0];
                float v1 = acc[mi][nj][rr * 2 + 1] + bb[nj][1];
                if (doRelu) { v0 = fmaxf(v0, 0.0f); v1 = fmaxf(v1, 0.0f); }
                *(float2*)(yr + nBase + nj * 8) = make_float2(v0, v1);
            }
        }
    }
}

// ---------------------------------------------------------------------------
// Epilogue: positional max of 3 convs, per-token L2 norm, transpose write,
// pooled word vector. One block per sample, 512 threads (one per feature).
// ---------------------------------------------------------------------------
__global__ void __launch_bounds__(512)
epilogue_kernel(float* __restrict__ words_out, float* __restrict__ word_vec)
{
    const int s = blockIdx.x;
    const int c = threadIdx.x;
    const int lane = c & 31;
    const int wid  = c >> 5;

    __shared__ float red[21][16];
    __shared__ float invn[21];

    const float* Ab = g_A + (size_t)s * 20 * FEAT + c;
    const float* Bb = g_B + (size_t)s * 19 * FEAT + c;
    const float* Cb = g_C + (size_t)s * 18 * FEAT + c;

    float code[20];
    float ma = 0.0f, mb = 0.0f, mc = 0.0f;

    #pragma unroll
    for (int t = 0; t < 20; t++) {
        float av = Ab[t * FEAT];
        float bv = (t < 19) ? Bb[t * FEAT] : 0.0f;   // relu >= 0: 0-pad exact
        float cv = (t < 18) ? Cb[t * FEAT] : 0.0f;
        ma = fmaxf(ma, av);
        mb = fmaxf(mb, bv);
        mc = fmaxf(mc, cv);
        float cd = fmaxf(av, fmaxf(bv, cv));
        code[t] = cd;
        float ss = cd * cd;
        #pragma unroll
        for (int o = 16; o > 0; o >>= 1) ss += __shfl_xor_sync(0xffffffffu, ss, o);
        if (lane == 0) red[t][wid] = ss;
    }

    float pooled = (ma + mb + mc) * (1.0f / 3.0f);
    {
        float ps = pooled * pooled;
        #pragma unroll
        for (int o = 16; o > 0; o >>= 1) ps += __shfl_xor_sync(0xffffffffu, ps, o);
        if (lane == 0) red[20][wid] = ps;
    }
    __syncthreads();

    if (c < 21) {
        float ssum = 0.0f;
        #pragma unroll
        for (int i = 0; i < 16; i++) ssum += red[c][i];
        invn[c] = 1.0f / fmaxf(sqrtf(ssum), 1e-12f);
    }
    __syncthreads();

    float* op = words_out + (size_t)s * FEAT * 20 + (size_t)c * 20;
    #pragma unroll
    for (int q = 0; q < 5; q++) {
        float4 v;
        v.x = code[q * 4 + 0] * invn[q * 4 + 0];
        v.y = code[q * 4 + 1] * invn[q * 4 + 1];
        v.z = code[q * 4 + 2] * invn[q * 4 + 2];
        v.w = code[q * 4 + 3] * invn[q * 4 + 3];
        *(float4*)(op + q * 4) = v;
    }
    word_vec[(size_t)s * FEAT + c] = pooled * invn[20];
}

// ---------------------------------------------------------------------------
extern "C" void kernel_launch(void* const* d_in, const int* in_sizes, int n_in,
                              void* d_out, int out_size)
{
    const float* words = (const float*)d_in[0];
    const float* sentE = (const float*)d_in[1];
    const float* W1 = (const float*)d_in[2];
    const float* b1 = (const float*)d_in[3];
    const float* W2 = (const float*)d_in[4];
    const float* b2 = (const float*)d_in[5];
    const float* W3 = (const float*)d_in[6];
    const float* b3 = (const float*)d_in[7];
    const float* Wp = (const float*)d_in[8];
    const float* bp = (const float*)d_in[9];

    float* out       = (float*)d_out;
    float* words_out = out;
    float* word_vec  = out + (size_t)BS * FEAT * 20;
    float* sent_out  = word_vec + (size_t)BS * FEAT;

    cudaFuncSetAttribute(gemm_mma, cudaFuncAttributeMaxDynamicSharedMemorySize,
                         SMEM_TOTAL);

    float* g_wt_base;
    cudaGetSymbolAddress((void**)&g_wt_base, g_Wt);
    float* wt1 = g_wt_base;
    float* wt2 = wt1 + (size_t)512 * 768;
    float* wt3 = wt2 + (size_t)512 * 1536;
    float* wtp = wt3 + (size_t)512 * 2304;

    transpose_w<<<dim3(768 / 32, 16),  dim3(32, 8)>>>(W1, wt1, 768);
    transpose_w<<<dim3(1536 / 32, 16), dim3(32, 8)>>>(W2, wt2, 1536);
    transpose_w<<<dim3(2304 / 32, 16), dim3(32, 8)>>>(W3, wt3, 2304);
    transpose_w<<<dim3(768 / 32, 16),  dim3(32, 8)>>>(Wp, wtp, 768);

    const int SSTRIDE = 20 * EMB;   // 15360

    // conv1: M=81920, K=768
    gemm_mma<<<dim3(640, 2), 256, SMEM_TOTAL>>>(words, wt1, b1, nullptr,
                                                0, 768, 20, SSTRIDE, 1);
    // conv2: M=77824, K=1536
    gemm_mma<<<dim3(608, 2), 256, SMEM_TOTAL>>>(words, wt2, b2, nullptr,
                                                1, 1536, 19, SSTRIDE, 1);
    // conv3: M=73728, K=2304
    gemm_mma<<<dim3(576, 2), 256, SMEM_TOTAL>>>(words, wt3, b3, nullptr,
                                                2, 2304, 18, SSTRIDE, 1);
    // sentence projection: M=4096, K=768
    gemm_mma<<<dim3(32, 2), 256, SMEM_TOTAL>>>(sentE, wtp, bp, sent_out,
                                               3, 768, 1, EMB, 0);

    epilogue_kernel<<<BS, 512>>>(words_out, word_vec);
}

// round 5
// speedup vs baseline: 1.8803x; 1.8803x over previous
#include <cuda_runtime.h>
#include <cuda_fp16.h>
#include <cstdint>

// ---------------------------------------------------------------------------
// BERTHeading via warp-level mma.sync fp16 GEMMs (f32 accumulate).
// fp16 has the same 10 mantissa bits as tf32 but k16 per MMA -> 2x K-density.
//   conv-k row (s,t) = relu( dot(words[s, t:t+k] (contig 768k), Wk) + bk )
// Tile: BM=128 x BN=256, K-chunk 32. 8 warps, 64x64 warp tile.
// 4-stage cp.async pipeline, ldmatrix.x4 fragments, KPAD=40 halves.
// ---------------------------------------------------------------------------

#define BS      4096
#define EMB     768
#define FEAT    512

#define BM      128
#define BN      256
#define BKF     32                  // K elements per chunk
#define KPH     40                  // halves stride (80 B, ldmatrix conflict-free)
#define A_STG_B (BM * KPH * 2)      // 10240 B
#define B_STG_B (BN * KPH * 2)      // 20480 B
#define STG_B   (A_STG_B + B_STG_B) // 30720 B
#define STAGES  4
#define SMEM_TOTAL (STAGES * STG_B) // 122880 B

__device__ float  g_A[BS * 20 * FEAT];
__device__ float  g_B[BS * 19 * FEAT];
__device__ float  g_C[BS * 18 * FEAT];
__device__ __half g_Xh[BS * 20 * EMB];     // fp16 words_emb
__device__ __half g_Sh[BS * EMB];          // fp16 sent_emb
// transposed fp16 weights, [512, K] row-major: W1 | W2 | W3 | Wp
__device__ __half g_Wth[512 * (768 + 1536 + 2304 + 768)];

#define CP_ASYNC16(saddr, gptr) \
    asm volatile("cp.async.cg.shared.global [%0], [%1], 16;" :: "r"(saddr), "l"(gptr))
#define CP_COMMIT() asm volatile("cp.async.commit_group;" ::: "memory")
#define CP_WAIT3()  asm volatile("cp.async.wait_group 3;" ::: "memory")

__device__ __forceinline__ uint32_t smem_u32(const void* p) {
    uint32_t a;
    asm("{ .reg .u64 t; cvta.to.shared.u64 t, %1; cvt.u32.u64 %0, t; }"
        : "=r"(a) : "l"(p));
    return a;
}

__device__ __forceinline__ void mma_f16(float* d, const uint32_t* a,
                                        const uint32_t* b) {
    asm volatile(
        "mma.sync.aligned.m16n8k16.row.col.f32.f16.f16.f32 "
        "{%0,%1,%2,%3}, {%4,%5,%6,%7}, {%8,%9}, {%0,%1,%2,%3};"
        : "+f"(d[0]), "+f"(d[1]), "+f"(d[2]), "+f"(d[3])
        : "r"(a[0]), "r"(a[1]), "r"(a[2]), "r"(a[3]), "r"(b[0]), "r"(b[1]));
}

__device__ __forceinline__ void ldsm_x4(uint32_t* r, uint32_t addr) {
    asm volatile(
        "ldmatrix.sync.aligned.m8n8.x4.shared.b16 {%0,%1,%2,%3}, [%4];"
        : "=r"(r[0]), "=r"(r[1]), "=r"(r[2]), "=r"(r[3]) : "r"(addr));
}

// ---------------------------------------------------------------------------
// f32 -> f16 conversion (vectorized), n multiple of 4
// ---------------------------------------------------------------------------
__global__ void cvt_f32_f16(const float* __restrict__ src,
                            __half* __restrict__ dst, int n4)
{
    int i = blockIdx.x * blockDim.x + threadIdx.x;
    if (i < n4) {
        float4 v = ((const float4*)src)[i];
        __half2* d = (__half2*)dst + 2 * (size_t)i;
        d[0] = __floats2half2_rn(v.x, v.y);
        d[1] = __floats2half2_rn(v.z, v.w);
    }
}

// ---------------------------------------------------------------------------
// Weight transpose + fp16 rounding: W [K,512] -> Wt [512,K] fp16
// ---------------------------------------------------------------------------
__global__ void transpose_w(const float* __restrict__ W, __half* __restrict__ Wt,
                            int K)
{
    __shared__ float t[32][33];
    const int kb = blockIdx.x * 32, nb = blockIdx.y * 32;
    const int x = threadIdx.x, y = threadIdx.y;   // 32 x 8
    #pragma unroll
    for (int i = 0; i < 32; i += 8)
        t[y + i][x] = W[(size_t)(kb + y + i) * FEAT + nb + x];
    __syncthreads();
    #pragma unroll
    for (int i = 0; i < 32; i += 8)
        Wt[(size_t)(nb + y + i) * K + kb + x] = __float2half_rn(t[x][y + i]);
}

// ---------------------------------------------------------------------------
// fp16 mma.sync GEMM.
//   Y[m, nb..nb+255] = act( A(m,:) @ Wt[nb..nb+255,:]^T + bias )
//   A(m,:) = X + (m/T)*srcStride + (m%T)*768, contiguous K halves.
// Grid: (M/128, 512/256). 256 threads.
// ---------------------------------------------------------------------------
__global__ void __launch_bounds__(256, 1)
gemm_f16(const __half* __restrict__ X, const __half* __restrict__ Wt,
         const float* __restrict__ bias, float* __restrict__ Yext,
         int sel, int K, int T, int srcStride, int doRelu)
{
    extern __shared__ char smem[];
    float* Y = (sel == 0) ? g_A : (sel == 1) ? g_B : (sel == 2) ? g_C : Yext;

    const int tid  = threadIdx.x;
    const int lane = tid & 31;
    const int wid  = tid >> 5;
    const int wm   = wid & 1;        // 2 m-warps
    const int wn   = wid >> 1;       // 4 n-warps
    const int r    = lane >> 2;      // 0..7
    const int cq   = lane & 3;       // 0..3

    const int nb = blockIdx.y * BN;
    const uint32_t sbase = smem_u32(smem);

    // ---- loader addresses ----
    // A: row = tid/2 (128 rows of 64 B), 2 x 16B at koff = (tid&1)*16 halves
    const int am = blockIdx.x * BM + (tid >> 1);
    const __half* aRow = X + (size_t)(am / T) * srcStride
                           + (size_t)(am % T) * EMB + (tid & 1) * 16;
    const uint32_t aDst = sbase + ((tid >> 1) * KPH + (tid & 1) * 16) * 2;
    // B: row = tid (256 rows of 64 B), 4 x 16B
    const __half* bRow = Wt + (size_t)(nb + tid) * K;
    const uint32_t bDst = sbase + A_STG_B + tid * KPH * 2;

    const int Kc = K / BKF;

    auto load_chunk = [&](int chunk) {
        const uint32_t so = (uint32_t)((chunk & (STAGES - 1)) * STG_B);
        const int kc = chunk * BKF;
        #pragma unroll
        for (int j = 0; j < 2; j++)
            CP_ASYNC16(aDst + so + j * 16, aRow + kc + j * 8);
        #pragma unroll
        for (int j = 0; j < 4; j++)
            CP_ASYNC16(bDst + so + j * 16, bRow + kc + j * 8);
    };

    float acc[4][8][4];
    #pragma unroll
    for (int mi = 0; mi < 4; mi++)
        #pragma unroll
        for (int nj = 0; nj < 8; nj++)
            #pragma unroll
            for (int q = 0; q < 4; q++) acc[mi][nj][q] = 0.0f;

    load_chunk(0); CP_COMMIT();
    load_chunk(1); CP_COMMIT();
    load_chunk(2); CP_COMMIT();

    // ldmatrix lane mapping (x4): lanes 0-7 -> matrix0 rows, 8-15 -> m1,
    // 16-23 -> m2, 24-31 -> m3. Matrices: {rows 0-7 @k0, rows 8-15 @k0,
    // rows 0-7 @k8, rows 8-15 @k8} of a 16-row x 16-half block.
    const int rowOff = ((lane >> 3) & 1) * 8 + (lane & 7);
    const int khOff  = (lane >> 4) * 8;
    const uint32_t aFragBase =
        sbase + ((wm * 64 + rowOff) * KPH + khOff) * 2;
    const uint32_t bFragBase =
        sbase + A_STG_B + ((wn * 64 + rowOff) * KPH + khOff) * 2;

    for (int c = 0; c < Kc; c++) {
        __syncthreads();                 // readers of stage (c+3)&3 done
        if (c + 3 < Kc) load_chunk(c + 3);
        CP_COMMIT();
        CP_WAIT3();                      // chunk c resident

        const uint32_t so = (uint32_t)((c & (STAGES - 1)) * STG_B);

        #pragma unroll
        for (int ks = 0; ks < 2; ks++) {       // two k16 steps per 32-chunk
            uint32_t af[4][4];
            #pragma unroll
            for (int mi = 0; mi < 4; mi++)
                ldsm_x4(af[mi], aFragBase + so + (mi * 16 * KPH + ks * 16) * 2);
            uint32_t bf[4][4];   // [njp]: {nEven.b0, nOdd.b0, nEven.b1, nOdd.b1}
            #pragma unroll
            for (int njp = 0; njp < 4; njp++)
                ldsm_x4(bf[njp], bFragBase + so + (njp * 16 * KPH + ks * 16) * 2);

            #pragma unroll
            for (int mi = 0; mi < 4; mi++)
                #pragma unroll
                for (int njp = 0; njp < 4; njp++) {
                    uint32_t b0[2] = { bf[njp][0], bf[njp][2] };
                    uint32_t b1[2] = { bf[njp][1], bf[njp][3] };
                    mma_f16(acc[mi][2 * njp + 0], af[mi], b0);
                    mma_f16(acc[mi][2 * njp + 1], af[mi], b1);
                }
        }
    }

    // ---- epilogue: bias (+relu), write Y ----
    const int mBase = blockIdx.x * BM + wm * 64 + r;
    const int nBase = nb + wn * 64 + cq * 2;
    float bb[8][2];
    #pragma unroll
    for (int nj = 0; nj < 8; nj++) {
        bb[nj][0] = __ldg(bias + nBase + nj * 8);
        bb[nj][1] = __ldg(bias + nBase + nj * 8 + 1);
    }
    #pragma unroll
    for (int mi = 0; mi < 4; mi++) {
        #pragma unroll
        for (int rr = 0; rr < 2; rr++) {
            float* yr = Y + (size_t)(mBase + mi * 16 + rr * 8) * FEAT;
            #pragma unroll
            for (int nj = 0; nj < 8; nj++) {
                float v0 = acc[mi][nj][rr * 2 + 0] + bb[nj][0];
                float v1 = acc[mi][nj][rr * 2 + 1] + bb[nj][1];
                if (doRelu) { v0 = fmaxf(v0, 0.0f); v1 = fmaxf(v1, 0.0f); }
                *(float2*)(yr + nBase + nj * 8) = make_float2(v0, v1);
            }
        }
    }
}

// ---------------------------------------------------------------------------
// Epilogue: positional max of 3 convs, per-token L2 norm, transpose write,
// pooled word vector. One block per sample, 512 threads (one per feature).
// ---------------------------------------------------------------------------
__global__ void __launch_bounds__(512)
epilogue_kernel(float* __restrict__ words_out, float* __restrict__ word_vec)
{
    const int s = blockIdx.x;
    const int c = threadIdx.x;
    const int lane = c & 31;
    const int wid  = c >> 5;

    __shared__ float red[21][16];
    __shared__ float invn[21];

    const float* Ab = g_A + (size_t)s * 20 * FEAT + c;
    const float* Bb = g_B + (size_t)s * 19 * FEAT + c;
    const float* Cb = g_C + (size_t)s * 18 * FEAT + c;

    float code[20];
    float ma = 0.0f, mb = 0.0f, mc = 0.0f;

    #pragma unroll
    for (int t = 0; t < 20; t++) {
        float av = Ab[t * FEAT];
        float bv = (t < 19) ? Bb[t * FEAT] : 0.0f;   // relu >= 0: 0-pad exact
        float cv = (t < 18) ? Cb[t * FEAT] : 0.0f;
        ma = fmaxf(ma, av);
        mb = fmaxf(mb, bv);
        mc = fmaxf(mc, cv);
        float cd = fmaxf(av, fmaxf(bv, cv));
        code[t] = cd;
        float ss = cd * cd;
        #pragma unroll
        for (int o = 16; o > 0; o >>= 1) ss += __shfl_xor_sync(0xffffffffu, ss, o);
        if (lane == 0) red[t][wid] = ss;
    }

    float pooled = (ma + mb + mc) * (1.0f / 3.0f);
    {
        float ps = pooled * pooled;
        #pragma unroll
        for (int o = 16; o > 0; o >>= 1) ps += __shfl_xor_sync(0xffffffffu, ps, o);
        if (lane == 0) red[20][wid] = ps;
    }
    __syncthreads();

    if (c < 21) {
        float ssum = 0.0f;
        #pragma unroll
        for (int i = 0; i < 16; i++) ssum += red[c][i];
        invn[c] = 1.0f / fmaxf(sqrtf(ssum), 1e-12f);
    }
    __syncthreads();

    float* op = words_out + (size_t)s * FEAT * 20 + (size_t)c * 20;
    #pragma unroll
    for (int q = 0; q < 5; q++) {
        float4 v;
        v.x = code[q * 4 + 0] * invn[q * 4 + 0];
        v.y = code[q * 4 + 1] * invn[q * 4 + 1];
        v.z = code[q * 4 + 2] * invn[q * 4 + 2];
        v.w = code[q * 4 + 3] * invn[q * 4 + 3];
        *(float4*)(op + q * 4) = v;
    }
    word_vec[(size_t)s * FEAT + c] = pooled * invn[20];
}

// ---------------------------------------------------------------------------
extern "C" void kernel_launch(void* const* d_in, const int* in_sizes, int n_in,
                              void* d_out, int out_size)
{
    const float* words = (const float*)d_in[0];
    const float* sentE = (const float*)d_in[1];
    const float* W1 = (const float*)d_in[2];
    const float* b1 = (const float*)d_in[3];
    const float* W2 = (const float*)d_in[4];
    const float* b2 = (const float*)d_in[5];
    const float* W3 = (const float*)d_in[6];
    const float* b3 = (const float*)d_in[7];
    const float* Wp = (const float*)d_in[8];
    const float* bp = (const float*)d_in[9];

    float* out       = (float*)d_out;
    float* words_out = out;
    float* word_vec  = out + (size_t)BS * FEAT * 20;
    float* sent_out  = word_vec + (size_t)BS * FEAT;

    cudaFuncSetAttribute(gemm_f16, cudaFuncAttributeMaxDynamicSharedMemorySize,
                         SMEM_TOTAL);

    __half *xh, *sh, *wth;
    cudaGetSymbolAddress((void**)&xh,  g_Xh);
    cudaGetSymbolAddress((void**)&sh,  g_Sh);
    cudaGetSymbolAddress((void**)&wth, g_Wth);
    __half* wt1 = wth;
    __half* wt2 = wt1 + (size_t)512 * 768;
    __half* wt3 = wt2 + (size_t)512 * 1536;
    __half* wtp = wt3 + (size_t)512 * 2304;

    // input conversions
    {
        int n4 = BS * 20 * EMB / 4;
        cvt_f32_f16<<<(n4 + 255) / 256, 256>>>(words, xh, n4);
        int s4 = BS * EMB / 4;
        cvt_f32_f16<<<(s4 + 255) / 256, 256>>>(sentE, sh, s4);
    }
    // weight transposes (fp16)
    transpose_w<<<dim3(768 / 32, 16),  dim3(32, 8)>>>(W1, wt1, 768);
    transpose_w<<<dim3(1536 / 32, 16), dim3(32, 8)>>>(W2, wt2, 1536);
    transpose_w<<<dim3(2304 / 32, 16), dim3(32, 8)>>>(W3, wt3, 2304);
    transpose_w<<<dim3(768 / 32, 16),  dim3(32, 8)>>>(Wp, wtp, 768);

    const int SSTRIDE = 20 * EMB;   // 15360

    // conv1: M=81920, K=768
    gemm_f16<<<dim3(640, 2), 256, SMEM_TOTAL>>>(xh, wt1, b1, nullptr,
                                                0, 768, 20, SSTRIDE, 1);
    // conv2: M=77824, K=1536
    gemm_f16<<<dim3(608, 2), 256, SMEM_TOTAL>>>(xh, wt2, b2, nullptr,
                                                1, 1536, 19, SSTRIDE, 1);
    // conv3: M=73728, K=2304
    gemm_f16<<<dim3(576, 2), 256, SMEM_TOTAL>>>(xh, wt3, b3, nullptr,
                                                2, 2304, 18, SSTRIDE, 1);
    // sentence projection: M=4096, K=768
    gemm_f16<<<dim3(32, 2), 256, SMEM_TOTAL>>>(sh, wtp, bp, sent_out,
                                               3, 768, 1, EMB, 0);

    epilogue_kernel<<<BS, 512>>>(words_out, word_vec);
}

// round 8
// speedup vs baseline: 2.4484x; 1.3021x over previous
#include <cuda_runtime.h>
#include <cuda_fp16.h>
#include <cstdint>

// ---------------------------------------------------------------------------
// BERTHeading via warp-level mma.sync fp16 GEMMs (f32 accumulate).
// One merged GEMM launch (4 segments), 512 threads/CTA (16 warps, 64x32 warp
// tile). 4-stage cp.async pipeline with the race-free protocol:
//   wait_group 2 -> __syncthreads -> prefetch(c+3) -> compute(c)
// ---------------------------------------------------------------------------

#define BS      4096
#define EMB     768
#define FEAT    512

#define BM      128
#define BN      256
#define BKF     32                  // K elements per chunk
#define KPH     40                  // halves stride (80 B, ldmatrix conflict-free)
#define A_STG_B (BM * KPH * 2)      // 10240 B
#define B_STG_B (BN * KPH * 2)      // 20480 B
#define STG_B   (A_STG_B + B_STG_B) // 30720 B
#define STAGES  4
#define SMEM_TOTAL (STAGES * STG_B) // 122880 B

__device__ float  g_A[BS * 20 * FEAT];
__device__ float  g_B[BS * 19 * FEAT];
__device__ float  g_C[BS * 18 * FEAT];
__device__ __half g_Xh[BS * 20 * EMB];     // fp16 words_emb
__device__ __half g_Sh[BS * EMB];          // fp16 sent_emb
// transposed fp16 weights, [512, K] row-major: W1 | W2 | W3 | Wp
__device__ __half g_Wth[512 * (768 + 1536 + 2304 + 768)];

struct Seg {
    const __half* X;
    const __half* Wt;
    const float*  bias;
    float*        Y;
    int K, T, srcStride, doRelu, blkStart;
};
struct Params { Seg seg[4]; };

#define CP_ASYNC16(saddr, gptr) \
    asm volatile("cp.async.cg.shared.global [%0], [%1], 16;" :: "r"(saddr), "l"(gptr))
#define CP_COMMIT() asm volatile("cp.async.commit_group;" ::: "memory")
#define CP_WAIT2()  asm volatile("cp.async.wait_group 2;" ::: "memory")

__device__ __forceinline__ uint32_t smem_u32(const void* p) {
    uint32_t a;
    asm("{ .reg .u64 t; cvta.to.shared.u64 t, %1; cvt.u32.u64 %0, t; }"
        : "=r"(a) : "l"(p));
    return a;
}

__device__ __forceinline__ void mma_f16(float* d, const uint32_t* a,
                                        const uint32_t* b) {
    asm volatile(
        "mma.sync.aligned.m16n8k16.row.col.f32.f16.f16.f32 "
        "{%0,%1,%2,%3}, {%4,%5,%6,%7}, {%8,%9}, {%0,%1,%2,%3};"
        : "+f"(d[0]), "+f"(d[1]), "+f"(d[2]), "+f"(d[3])
        : "r"(a[0]), "r"(a[1]), "r"(a[2]), "r"(a[3]), "r"(b[0]), "r"(b[1]));
}

__device__ __forceinline__ void ldsm_x4(uint32_t* r, uint32_t addr) {
    asm volatile(
        "ldmatrix.sync.aligned.m8n8.x4.shared.b16 {%0,%1,%2,%3}, [%4];"
        : "=r"(r[0]), "=r"(r[1]), "=r"(r[2]), "=r"(r[3]) : "r"(addr));
}

// ---------------------------------------------------------------------------
// f32 -> f16 conversion (vectorized), n multiple of 4
// ---------------------------------------------------------------------------
__global__ void cvt_f32_f16(const float* __restrict__ src,
                            __half* __restrict__ dst, int n4)
{
    int i = blockIdx.x * blockDim.x + threadIdx.x;
    if (i < n4) {
        float4 v = ((const float4*)src)[i];
        __half2* d = (__half2*)dst + 2 * (size_t)i;
        d[0] = __floats2half2_rn(v.x, v.y);
        d[1] = __floats2half2_rn(v.z, v.w);
    }
}

// ---------------------------------------------------------------------------
// Weight transpose + fp16 rounding: W [K,512] -> Wt [512,K] fp16
// ---------------------------------------------------------------------------
__global__ void transpose_w(const float* __restrict__ W, __half* __restrict__ Wt,
                            int K)
{
    __shared__ float t[32][33];
    const int kb = blockIdx.x * 32, nb = blockIdx.y * 32;
    const int x = threadIdx.x, y = threadIdx.y;   // 32 x 8
    #pragma unroll
    for (int i = 0; i < 32; i += 8)
        t[y + i][x] = W[(size_t)(kb + y + i) * FEAT + nb + x];
    __syncthreads();
    #pragma unroll
    for (int i = 0; i < 32; i += 8)
        Wt[(size_t)(nb + y + i) * K + kb + x] = __float2half_rn(t[x][y + i]);
}

// ---------------------------------------------------------------------------
// Merged fp16 mma.sync GEMM (4 segments in one grid).
//   Y[m, nb..nb+255] = act( A(m,:) @ Wt[nb..nb+255,:]^T + bias )
//   A(m,:) = X + (m/T)*srcStride + (m%T)*768, contiguous K halves.
// 512 threads: 16 warps, 2 m-warps x 8 n-warps, 64x32 warp tile.
// ---------------------------------------------------------------------------
__global__ void __launch_bounds__(512, 1)
gemm_f16(Params p)
{
    extern __shared__ char smem[];
    const int bid = blockIdx.x;
    const int sid = (bid >= p.seg[1].blkStart) + (bid >= p.seg[2].blkStart)
                  + (bid >= p.seg[3].blkStart);
    const Seg sg = p.seg[sid];

    const int idx = bid - sg.blkStart;
    const int mb  = idx >> 1;          // m-tile
    const int nb  = (idx & 1) * BN;    // n offset (FEAT/BN == 2)

    const int tid  = threadIdx.x;
    const int lane = tid & 31;
    const int wid  = tid >> 5;         // 0..15
    const int wm   = wid & 1;          // 2 m-warps (64 rows each)
    const int wn   = wid >> 1;         // 8 n-warps (32 cols each)
    const int r    = lane >> 2;        // 0..7
    const int cq   = lane & 3;         // 0..3

    const uint32_t sbase = smem_u32(smem);

    // ---- loader addresses (512 threads) ----
    // A: 128 rows x 64 B; thread t -> row t/4, 16B chunk t%4 (1 cp.async)
    const int am = mb * BM + (tid >> 2);
    const __half* aRow = sg.X + (size_t)(am / sg.T) * sg.srcStride
                              + (size_t)(am % sg.T) * EMB + (tid & 3) * 8;
    const uint32_t aDst = sbase + ((tid >> 2) * KPH + (tid & 3) * 8) * 2;
    // B: 256 rows x 64 B; thread t -> row t/2, 32 B half (2 cp.async of 16 B)
    const __half* bRow = sg.Wt + (size_t)(nb + (tid >> 1)) * sg.K + (tid & 1) * 16;
    const uint32_t bDst = sbase + A_STG_B
                        + ((tid >> 1) * KPH + (tid & 1) * 16) * 2;

    const int Kc = sg.K / BKF;

    auto load_chunk = [&](int chunk) {
        const uint32_t so = (uint32_t)((chunk & (STAGES - 1)) * STG_B);
        const int kc = chunk * BKF;
        CP_ASYNC16(aDst + so, aRow + kc);
        CP_ASYNC16(bDst + so,      bRow + kc);       // bytes [x*32, x*32+16)
        CP_ASYNC16(bDst + so + 16, bRow + kc + 8);   // bytes [x*32+16, x*32+32)
    };

    float acc[4][4][4];
    #pragma unroll
    for (int mi = 0; mi < 4; mi++)
        #pragma unroll
        for (int nj = 0; nj < 4; nj++)
            #pragma unroll
            for (int q = 0; q < 4; q++) acc[mi][nj][q] = 0.0f;

    load_chunk(0); CP_COMMIT();
    load_chunk(1); CP_COMMIT();
    load_chunk(2); CP_COMMIT();

    // ldmatrix.x4 lane mapping: matrices {rows0-7@k0, rows8-15@k0,
    // rows0-7@k8, rows8-15@k8} of a 16x16-half block.
    const int rowOff = ((lane >> 3) & 1) * 8 + (lane & 7);
    const int khOff  = (lane >> 4) * 8;
    const uint32_t aFragBase =
        sbase + ((wm * 64 + rowOff) * KPH + khOff) * 2;
    const uint32_t bFragBase =
        sbase + A_STG_B + ((wn * 32 + rowOff) * KPH + khOff) * 2;

    for (int c = 0; c < Kc; c++) {
        // Race-free protocol:
        CP_WAIT2();                      // own cp.asyncs for chunk c landed
        __syncthreads();                 // => everyone's chunk c landed, and
                                         //    all warps finished reading c-1
        if (c + 3 < Kc) load_chunk(c + 3);   // overwrites stage of c-1: safe
        CP_COMMIT();                     // (possibly empty group; keeps count)

        const uint32_t so = (uint32_t)((c & (STAGES - 1)) * STG_B);

        #pragma unroll
        for (int ks = 0; ks < 2; ks++) {       // two k16 steps per 32-chunk
            uint32_t af[4][4];
            #pragma unroll
            for (int mi = 0; mi < 4; mi++)
                ldsm_x4(af[mi], aFragBase + so + (mi * 16 * KPH + ks * 16) * 2);
            uint32_t bf[2][4];   // [njp]: {nEven.b0, nOdd.b0, nEven.b1, nOdd.b1}
            #pragma unroll
            for (int njp = 0; njp < 2; njp++)
                ldsm_x4(bf[njp], bFragBase + so + (njp * 16 * KPH + ks * 16) * 2);

            #pragma unroll
            for (int mi = 0; mi < 4; mi++)
                #pragma unroll
                for (int njp = 0; njp < 2; njp++) {
                    uint32_t b0[2] = { bf[njp][0], bf[njp][2] };
                    uint32_t b1[2] = { bf[njp][1], bf[njp][3] };
                    mma_f16(acc[mi][2 * njp + 0], af[mi], b0);
                    mma_f16(acc[mi][2 * njp + 1], af[mi], b1);
                }
        }
    }

    // ---- epilogue: bias (+relu), write Y ----
    const int mBase = mb * BM + wm * 64 + r;
    const int nBase = nb + wn * 32 + cq * 2;
    float bb[4][2];
    #pragma unroll
    for (int nj = 0; nj < 4; nj++) {
        bb[nj][0] = __ldg(sg.bias + nBase + nj * 8);
        bb[nj][1] = __ldg(sg.bias + nBase + nj * 8 + 1);
    }
    #pragma unroll
    for (int mi = 0; mi < 4; mi++) {
        #pragma unroll
        for (int rr = 0; rr < 2; rr++) {
            float* yr = sg.Y + (size_t)(mBase + mi * 16 + rr * 8) * FEAT;
            #pragma unroll
            for (int nj = 0; nj < 4; nj++) {
                float v0 = acc[mi][nj][rr * 2 + 0] + bb[nj][0];
                float v1 = acc[mi][nj][rr * 2 + 1] + bb[nj][1];
                if (sg.doRelu) { v0 = fmaxf(v0, 0.0f); v1 = fmaxf(v1, 0.0f); }
                *(float2*)(yr + nBase + nj * 8) = make_float2(v0, v1);
            }
        }
    }
}

// ---------------------------------------------------------------------------
// Epilogue: positional max of 3 convs, per-token L2 norm, transpose write,
// pooled word vector. One block per sample, 512 threads (one per feature).
// ---------------------------------------------------------------------------
__global__ void __launch_bounds__(512)
epilogue_kernel(float* __restrict__ words_out, float* __restrict__ word_vec)
{
    const int s = blockIdx.x;
    const int c = threadIdx.x;
    const int lane = c & 31;
    const int wid  = c >> 5;

    __shared__ float red[21][16];
    __shared__ float invn[21];

    const float* Ab = g_A + (size_t)s * 20 * FEAT + c;
    const float* Bb = g_B + (size_t)s * 19 * FEAT + c;
    const float* Cb = g_C + (size_t)s * 18 * FEAT + c;

    float code[20];
    float ma = 0.0f, mb = 0.0f, mc = 0.0f;

    #pragma unroll
    for (int t = 0; t < 20; t++) {
        float av = Ab[t * FEAT];
        float bv = (t < 19) ? Bb[t * FEAT] : 0.0f;   // relu >= 0: 0-pad exact
        float cv = (t < 18) ? Cb[t * FEAT] : 0.0f;
        ma = fmaxf(ma, av);
        mb = fmaxf(mb, bv);
        mc = fmaxf(mc, cv);
        float cd = fmaxf(av, fmaxf(bv, cv));
        code[t] = cd;
        float ss = cd * cd;
        #pragma unroll
        for (int o = 16; o > 0; o >>= 1) ss += __shfl_xor_sync(0xffffffffu, ss, o);
        if (lane == 0) red[t][wid] = ss;
    }

    float pooled = (ma + mb + mc) * (1.0f / 3.0f);
    {
        float ps = pooled * pooled;
        #pragma unroll
        for (int o = 16; o > 0; o >>= 1) ps += __shfl_xor_sync(0xffffffffu, ps, o);
        if (lane == 0) red[20][wid] = ps;
    }
    __syncthreads();

    if (c < 21) {
        float ssum = 0.0f;
        #pragma unroll
        for (int i = 0; i < 16; i++) ssum += red[c][i];
        invn[c] = 1.0f / fmaxf(sqrtf(ssum), 1e-12f);
    }
    __syncthreads();

    float* op = words_out + (size_t)s * FEAT * 20 + (size_t)c * 20;
    #pragma unroll
    for (int q = 0; q < 5; q++) {
        float4 v;
        v.x = code[q * 4 + 0] * invn[q * 4 + 0];
        v.y = code[q * 4 + 1] * invn[q * 4 + 1];
        v.z = code[q * 4 + 2] * invn[q * 4 + 2];
        v.w = code[q * 4 + 3] * invn[q * 4 + 3];
        *(float4*)(op + q * 4) = v;
    }
    word_vec[(size_t)s * FEAT + c] = pooled * invn[20];
}

// ---------------------------------------------------------------------------
extern "C" void kernel_launch(void* const* d_in, const int* in_sizes, int n_in,
                              void* d_out, int out_size)
{
    const float* words = (const float*)d_in[0];
    const float* sentE = (const float*)d_in[1];
    const float* W1 = (const float*)d_in[2];
    const float* b1 = (const float*)d_in[3];
    const float* W2 = (const float*)d_in[4];
    const float* b2 = (const float*)d_in[5];
    const float* W3 = (const float*)d_in[6];
    const float* b3 = (const float*)d_in[7];
    const float* Wp = (const float*)d_in[8];
    const float* bp = (const float*)d_in[9];

    float* out       = (float*)d_out;
    float* words_out = out;
    float* word_vec  = out + (size_t)BS * FEAT * 20;
    float* sent_out  = word_vec + (size_t)BS * FEAT;

    cudaFuncSetAttribute(gemm_f16, cudaFuncAttributeMaxDynamicSharedMemorySize,
                         SMEM_TOTAL);

    __half *xh, *sh, *wth;
    cudaGetSymbolAddress((void**)&xh,  g_Xh);
    cudaGetSymbolAddress((void**)&sh,  g_Sh);
    cudaGetSymbolAddress((void**)&wth, g_Wth);
    float *gA, *gB, *gC;
    cudaGetSymbolAddress((void**)&gA, g_A);
    cudaGetSymbolAddress((void**)&gB, g_B);
    cudaGetSymbolAddress((void**)&gC, g_C);
    __half* wt1 = wth;
    __half* wt2 = wt1 + (size_t)512 * 768;
    __half* wt3 = wt2 + (size_t)512 * 1536;
    __half* wtp = wt3 + (size_t)512 * 2304;

    // input conversions
    {
        int n4 = BS * 20 * EMB / 4;
        cvt_f32_f16<<<(n4 + 255) / 256, 256>>>(words, xh, n4);
        int s4 = BS * EMB / 4;
        cvt_f32_f16<<<(s4 + 255) / 256, 256>>>(sentE, sh, s4);
    }
    // weight transposes (fp16)
    transpose_w<<<dim3(768 / 32, 16),  dim3(32, 8)>>>(W1, wt1, 768);
    transpose_w<<<dim3(1536 / 32, 16), dim3(32, 8)>>>(W2, wt2, 1536);
    transpose_w<<<dim3(2304 / 32, 16), dim3(32, 8)>>>(W3, wt3, 2304);
    transpose_w<<<dim3(768 / 32, 16),  dim3(32, 8)>>>(Wp, wtp, 768);

    const int SSTRIDE = 20 * EMB;   // 15360

    // Merged GEMM: segments ordered longest-K first (conv3, conv2, conv1, sent)
    Params p;
    // conv3: M=73728 -> 576 mb x 2 = 1152 blocks
    p.seg[0] = { xh, wt3, b3, gC,       2304, 18, SSTRIDE, 1, 0 };
    // conv2: M=77824 -> 608 x 2 = 1216
    p.seg[1] = { xh, wt2, b2, gB,       1536, 19, SSTRIDE, 1, 1152 };
    // conv1: M=81920 -> 640 x 2 = 1280
    p.seg[2] = { xh, wt1, b1, gA,        768, 20, SSTRIDE, 1, 2368 };
    // sent:  M=4096  -> 32 x 2 = 64
    p.seg[3] = { sh, wtp, bp, sent_out,  768,  1, EMB,     0, 3648 };

    gemm_f16<<<3712, 512, SMEM_TOTAL>>>(p);

    epilogue_kernel<<<BS, 512>>>(words_out, word_vec);
}